// round 5
// baseline (speedup 1.0000x reference)
#include <cuda_runtime.h>
#include <cstdint>
#include <math.h>

// ---------------- fast-math row loss (tolerance 1e-3, margin ~5e-8) --------
__device__ __forceinline__ float row_loss(const float* __restrict__ p,
                                          const float* __restrict__ t) {
    float dx = p[0] - t[0];
    float dy = p[1] - t[1];

    float wp = fminf(fmaxf(p[2], 1e-7f), 1e7f);
    float hp = fminf(fmaxf(p[3], 1e-7f), 1e7f);
    float ap = 0.25f * wp * wp;
    float bp = 0.25f * hp * hp;
    float sp, cp;
    __sincosf(p[4], &sp, &cp);
    float cp2 = cp * cp, sp2 = sp * sp;
    float p00 = ap * cp2 + bp * sp2;
    float p11 = ap * sp2 + bp * cp2;
    float p01 = (ap - bp) * sp * cp;

    float wt = fminf(fmaxf(t[2], 1e-7f), 1e7f);
    float ht = fminf(fmaxf(t[3], 1e-7f), 1e7f);
    float at = 0.25f * wt * wt;
    float bt = 0.25f * ht * ht;
    float st, ct;
    __sincosf(t[4], &st, &ct);
    float ct2 = ct * ct, st2 = st * st;
    float t00 = at * ct2 + bt * st2;
    float t11 = at * st2 + bt * ct2;
    float t01 = (at - bt) * st * ct;

    float det_p = p00 * p11 - p01 * p01;
    float det_t = t00 * t11 - t01 * t01;
    float inv_det_t = __fdividef(1.0f, det_t);

    float term1 = (dx * dx * t11 - 2.0f * dx * dy * t01 + dy * dy * t00) * inv_det_t;
    float tr = (t11 * p00 + t00 * p11 - 2.0f * t01 * p01) * inv_det_t;

    float dis = term1 + tr + __logf(__fdividef(det_t, det_p)) - 2.0f;
    float kl = fmaxf(dis, 1e-6f);
    float L = __logf(1.0f + kl);
    return __fdividef(L, 1.0f + L);      // 1 - 1/(1+L), tau = 1
}

// ---------------- TMA bulk pipeline ----------------------------------------
#define STAGES 4
#define TILE_ROWS 256
#define TILE_FLOATS (TILE_ROWS * 5)          // 1280 floats
#define TILE_BYTES  (TILE_FLOATS * 4)        // 5120 bytes
#define CTAS_PER_SM 5                        // 5 x 41KB smem = 205KB <= 228KB

__device__ __forceinline__ uint32_t smem_u32(const void* p) {
    return (uint32_t)__cvta_generic_to_shared(p);
}

__device__ __forceinline__ void mbar_init(uint32_t bar, uint32_t count) {
    asm volatile("mbarrier.init.shared.b64 [%0], %1;" :: "r"(bar), "r"(count) : "memory");
}

__device__ __forceinline__ void mbar_expect_tx(uint32_t bar, uint32_t bytes) {
    asm volatile("mbarrier.arrive.expect_tx.shared.b64 _, [%0], %1;"
                 :: "r"(bar), "r"(bytes) : "memory");
}

__device__ __forceinline__ void bulk_ld(uint32_t dst_smem, const void* src,
                                        uint32_t bytes, uint32_t bar) {
    asm volatile(
        "cp.async.bulk.shared::cta.global.mbarrier::complete_tx::bytes "
        "[%0], [%1], %2, [%3];"
        :: "r"(dst_smem), "l"(src), "r"(bytes), "r"(bar) : "memory");
}

__device__ __forceinline__ void mbar_wait(uint32_t bar, uint32_t parity) {
    asm volatile(
        "{\n\t"
        ".reg .pred P;\n\t"
        "WAIT_%=:\n\t"
        "mbarrier.try_wait.parity.acquire.cta.shared::cta.b64 P, [%0], %1, 0x989680;\n\t"
        "@P bra WAIT_DONE_%=;\n\t"
        "bra WAIT_%=;\n\t"
        "WAIT_DONE_%=:\n\t"
        "}"
        :: "r"(bar), "r"(parity) : "memory");
}

__global__ void __launch_bounds__(256, CTAS_PER_SM)
kld_tma_kernel(const char* __restrict__ pred, const char* __restrict__ targ,
               float* __restrict__ out, int ntiles) {
    __shared__ alignas(128) float sp[STAGES][TILE_FLOATS];
    __shared__ alignas(128) float st[STAGES][TILE_FLOATS];
    __shared__ alignas(8)   uint64_t mbar[STAGES];

    const int tid = threadIdx.x;

    if (tid == 0) {
#pragma unroll
        for (int s = 0; s < STAGES; s++)
            mbar_init(smem_u32(&mbar[s]), 1);
        asm volatile("fence.proxy.async.shared::cta;" ::: "memory");
    }
    __syncthreads();

    // prologue: fill the pipeline
    if (tid == 0) {
#pragma unroll
        for (int s = 0; s < STAGES; s++) {
            long long tile = (long long)blockIdx.x + (long long)s * gridDim.x;
            if (tile < ntiles) {
                uint32_t bar = smem_u32(&mbar[s]);
                mbar_expect_tx(bar, 2 * TILE_BYTES);
                bulk_ld(smem_u32(&sp[s][0]), pred + tile * TILE_BYTES, TILE_BYTES, bar);
                bulk_ld(smem_u32(&st[s][0]), targ + tile * TILE_BYTES, TILE_BYTES, bar);
            }
        }
    }

    int j = 0;
    for (long long tile = blockIdx.x; tile < ntiles;
         tile += gridDim.x, j++) {
        int s  = j & (STAGES - 1);
        int ph = (j >> 2) & 1;
        mbar_wait(smem_u32(&mbar[s]), ph);

        float r = row_loss(&sp[s][5 * tid], &st[s][5 * tid]);
        out[tile * TILE_ROWS + tid] = r;       // coalesced STG.32

        __syncthreads();                       // all lanes done with stage s
        long long next = tile + (long long)STAGES * gridDim.x;
        if (tid == 0 && next < ntiles) {
            uint32_t bar = smem_u32(&mbar[s]);
            mbar_expect_tx(bar, 2 * TILE_BYTES);
            bulk_ld(smem_u32(&sp[s][0]), pred + next * TILE_BYTES, TILE_BYTES, bar);
            bulk_ld(smem_u32(&st[s][0]), targ + next * TILE_BYTES, TILE_BYTES, bar);
        }
    }
}

// Scalar tail for rows not covered by full 256-row tiles (not hit for N=4M).
__global__ void kld_loss_tail_kernel(const float* __restrict__ pred,
                                     const float* __restrict__ targ,
                                     float* __restrict__ out,
                                     int start, int n) {
    int i = start + blockIdx.x * blockDim.x + threadIdx.x;
    if (i >= n) return;
    out[i] = row_loss(pred + 5 * i, targ + 5 * i);
}

extern "C" void kernel_launch(void* const* d_in, const int* in_sizes, int n_in,
                              void* d_out, int out_size) {
    const float* pred = (const float*)d_in[0];
    const float* targ = (const float*)d_in[1];
    float* out = (float*)d_out;

    int n = in_sizes[0] / 5;       // rows
    int ntiles = n / TILE_ROWS;    // 15625 for N=4M
    int rem_start = ntiles * TILE_ROWS;

    if (ntiles > 0) {
        int grid = 152 * CTAS_PER_SM;   // 760 persistent CTAs
        if (grid > ntiles) grid = ntiles;
        kld_tma_kernel<<<grid, 256>>>((const char*)pred, (const char*)targ,
                                      out, ntiles);
    }
    if (rem_start < n) {
        int rem = n - rem_start;
        kld_loss_tail_kernel<<<(rem + 127) / 128, 128>>>(pred, targ, out,
                                                         rem_start, n);
    }
}

// round 6
// speedup vs baseline: 1.0693x; 1.0693x over previous
#include <cuda_runtime.h>
#include <math.h>

// Per-row KLD loss between two rotated boxes expressed as 2D Gaussians.
// Fast-math intrinsics: tolerance 1e-3, measured accuracy margin ~5e-8.
__device__ __forceinline__ float row_loss(const float* __restrict__ p,
                                          const float* __restrict__ t) {
    float dx = p[0] - t[0];
    float dy = p[1] - t[1];

    float wp = fminf(fmaxf(p[2], 1e-7f), 1e7f);
    float hp = fminf(fmaxf(p[3], 1e-7f), 1e7f);
    float ap = 0.25f * wp * wp;
    float bp = 0.25f * hp * hp;
    float sp, cp;
    __sincosf(p[4], &sp, &cp);           // |r| < pi/2: MUFU path accurate
    float cp2 = cp * cp, sp2 = sp * sp;
    float p00 = ap * cp2 + bp * sp2;
    float p11 = ap * sp2 + bp * cp2;
    float p01 = (ap - bp) * sp * cp;

    float wt = fminf(fmaxf(t[2], 1e-7f), 1e7f);
    float ht = fminf(fmaxf(t[3], 1e-7f), 1e7f);
    float at = 0.25f * wt * wt;
    float bt = 0.25f * ht * ht;
    float st, ct;
    __sincosf(t[4], &st, &ct);
    float ct2 = ct * ct, st2 = st * st;
    float t00 = at * ct2 + bt * st2;
    float t11 = at * st2 + bt * ct2;
    float t01 = (at - bt) * st * ct;

    float det_p = p00 * p11 - p01 * p01;
    float det_t = t00 * t11 - t01 * t01;
    float inv_det_t = __fdividef(1.0f, det_t);

    float term1 = (dx * dx * t11 - 2.0f * dx * dy * t01 + dy * dy * t00) * inv_det_t;
    float tr = (t11 * p00 + t00 * p11 - 2.0f * t01 * p01) * inv_det_t;

    float dis = term1 + tr + __logf(__fdividef(det_t, det_p)) - 2.0f;
    float kl = fmaxf(dis, 1e-6f);
    float L = __logf(1.0f + kl);
    return __fdividef(L, 1.0f + L);      // 1 - 1/(1+L), tau = 1
}

// Vectorized: each thread handles 4 rows = 20 floats = 5 float4 loads per
// input, marked evict-first streaming (.cs) — this data is single-touch; keep
// it from occupying L2 at normal priority. Stores likewise streaming.
__global__ void __launch_bounds__(256, 5)
kld_loss_vec4_kernel(const float4* __restrict__ pred,
                     const float4* __restrict__ targ,
                     float4* __restrict__ out, int n4) {
    int i = blockIdx.x * blockDim.x + threadIdx.x;
    if (i >= n4) return;

    float4 pv[5], tv[5];
#pragma unroll
    for (int k = 0; k < 5; k++) {
        pv[k] = __ldcs(&pred[5 * i + k]);
        tv[k] = __ldcs(&targ[5 * i + k]);
    }
    const float* pf = reinterpret_cast<const float*>(pv);
    const float* tf = reinterpret_cast<const float*>(tv);

    float4 r;
    r.x = row_loss(pf + 0,  tf + 0);
    r.y = row_loss(pf + 5,  tf + 5);
    r.z = row_loss(pf + 10, tf + 10);
    r.w = row_loss(pf + 15, tf + 15);
    __stcs(&out[i], r);
}

// Scalar tail for n % 4 != 0 (not hit for N=4M, kept for safety).
__global__ void kld_loss_tail_kernel(const float* __restrict__ pred,
                                     const float* __restrict__ targ,
                                     float* __restrict__ out,
                                     int start, int n) {
    int i = start + blockIdx.x * blockDim.x + threadIdx.x;
    if (i >= n) return;
    out[i] = row_loss(pred + 5 * i, targ + 5 * i);
}

extern "C" void kernel_launch(void* const* d_in, const int* in_sizes, int n_in,
                              void* d_out, int out_size) {
    const float* pred = (const float*)d_in[0];
    const float* targ = (const float*)d_in[1];
    float* out = (float*)d_out;

    int n = in_sizes[0] / 5;   // number of rows
    int n4 = n / 4;
    int rem_start = n4 * 4;

    if (n4 > 0) {
        const int threads = 256;
        int blocks = (n4 + threads - 1) / threads;
        kld_loss_vec4_kernel<<<blocks, threads>>>(
            (const float4*)pred, (const float4*)targ, (float4*)out, n4);
    }
    if (rem_start < n) {
        int rem = n - rem_start;
        kld_loss_tail_kernel<<<(rem + 127) / 128, 128>>>(pred, targ, out,
                                                         rem_start, n);
    }
}

// round 7
// speedup vs baseline: 1.1291x; 1.0559x over previous
#include <cuda_runtime.h>
#include <math.h>

// Per-row KLD loss between two rotated boxes expressed as 2D Gaussians.
// Fast-math intrinsics: tolerance 1e-3, measured accuracy margin ~5e-8.
__device__ __forceinline__ float row_loss(const float* __restrict__ p,
                                          const float* __restrict__ t) {
    float dx = p[0] - t[0];
    float dy = p[1] - t[1];

    float wp = fminf(fmaxf(p[2], 1e-7f), 1e7f);
    float hp = fminf(fmaxf(p[3], 1e-7f), 1e7f);
    float ap = 0.25f * wp * wp;
    float bp = 0.25f * hp * hp;
    float sp, cp;
    __sincosf(p[4], &sp, &cp);           // |r| < pi/2: MUFU path accurate
    float cp2 = cp * cp, sp2 = sp * sp;
    float p00 = ap * cp2 + bp * sp2;
    float p11 = ap * sp2 + bp * cp2;
    float p01 = (ap - bp) * sp * cp;

    float wt = fminf(fmaxf(t[2], 1e-7f), 1e7f);
    float ht = fminf(fmaxf(t[3], 1e-7f), 1e7f);
    float at = 0.25f * wt * wt;
    float bt = 0.25f * ht * ht;
    float st, ct;
    __sincosf(t[4], &st, &ct);
    float ct2 = ct * ct, st2 = st * st;
    float t00 = at * ct2 + bt * st2;
    float t11 = at * st2 + bt * ct2;
    float t01 = (at - bt) * st * ct;

    float det_p = p00 * p11 - p01 * p01;
    float det_t = t00 * t11 - t01 * t01;
    float inv_det_t = __fdividef(1.0f, det_t);

    float term1 = (dx * dx * t11 - 2.0f * dx * dy * t01 + dy * dy * t00) * inv_det_t;
    float tr = (t11 * p00 + t00 * p11 - 2.0f * t01 * p01) * inv_det_t;

    float dis = term1 + tr + __logf(__fdividef(det_t, det_p)) - 2.0f;
    float kl = fmaxf(dis, 1e-6f);
    float L = __logf(1.0f + kl);
    return __fdividef(L, 1.0f + L);      // 1 - 1/(1+L), tau = 1
}

// Persistent, software-pipelined: each thread grid-strides over 4-row groups
// (5 float4 per input per group). Iteration i+1's loads are issued BEFORE
// iteration i's math, so LDG issue is decoupled from compute and each warp
// keeps 160B continuously in flight across ~13 iterations — no per-wave
// load-burst / ramp gaps.
__global__ void __launch_bounds__(256, 2)
kld_loss_pipe_kernel(const float4* __restrict__ pred,
                     const float4* __restrict__ targ,
                     float4* __restrict__ out, int n4) {
    const int stride = gridDim.x * blockDim.x;
    int i = blockIdx.x * blockDim.x + threadIdx.x;
    if (i >= n4) return;

    float4 pc[5], tc[5];     // current buffers
    float4 pn[5], tn[5];     // prefetch buffers

#pragma unroll
    for (int k = 0; k < 5; k++) {
        pc[k] = __ldcs(&pred[5 * (size_t)i + k]);
        tc[k] = __ldcs(&targ[5 * (size_t)i + k]);
    }

#pragma unroll 1
    while (true) {
        int inext = i + stride;
        bool has_next = inext < n4;
        if (has_next) {
#pragma unroll
            for (int k = 0; k < 5; k++) {
                pn[k] = __ldcs(&pred[5 * (size_t)inext + k]);
                tn[k] = __ldcs(&targ[5 * (size_t)inext + k]);
            }
        }

        const float* pf = reinterpret_cast<const float*>(pc);
        const float* tf = reinterpret_cast<const float*>(tc);
        float4 r;
        r.x = row_loss(pf + 0,  tf + 0);
        r.y = row_loss(pf + 5,  tf + 5);
        r.z = row_loss(pf + 10, tf + 10);
        r.w = row_loss(pf + 15, tf + 15);
        __stcs(&out[i], r);

        if (!has_next) break;
#pragma unroll
        for (int k = 0; k < 5; k++) {
            pc[k] = pn[k];
            tc[k] = tn[k];
        }
        i = inext;
    }
}

// Scalar tail for n % 4 != 0 (not hit for N=4M, kept for safety).
__global__ void kld_loss_tail_kernel(const float* __restrict__ pred,
                                     const float* __restrict__ targ,
                                     float* __restrict__ out,
                                     int start, int n) {
    int i = start + blockIdx.x * blockDim.x + threadIdx.x;
    if (i >= n) return;
    out[i] = row_loss(pred + 5 * i, targ + 5 * i);
}

extern "C" void kernel_launch(void* const* d_in, const int* in_sizes, int n_in,
                              void* d_out, int out_size) {
    const float* pred = (const float*)d_in[0];
    const float* targ = (const float*)d_in[1];
    float* out = (float*)d_out;

    int n = in_sizes[0] / 5;   // number of rows
    int n4 = n / 4;
    int rem_start = n4 * 4;

    if (n4 > 0) {
        const int threads = 256;
        int grid = 152 * 2;                 // persistent: 2 CTAs per SM
        int max_grid = (n4 + threads - 1) / threads;
        if (grid > max_grid) grid = max_grid;
        kld_loss_pipe_kernel<<<grid, threads>>>(
            (const float4*)pred, (const float4*)targ, (float4*)out, n4);
    }
    if (rem_start < n) {
        int rem = n - rem_start;
        kld_loss_tail_kernel<<<(rem + 127) / 128, 128>>>(pred, targ, out,
                                                         rem_start, n);
    }
}